// round 8
// baseline (speedup 1.0000x reference)
#include <cuda_runtime.h>
#include <cuda_bf16.h>
#include <cstdint>

#define N_NODES 50000
#define IN_FEAT 64
#define HID 32
#define NG 128

// ---------------- scratch (static device globals; no allocs allowed) --------
__device__ float g_h[N_NODES * HID];
__device__ float g_T[N_NODES * HID];
__device__ float g_acc[N_NODES * HID];
__device__ float g_sums[NG * HID];
__device__ float g_cnt[NG];
__device__ int   g_is64;
// prepped bf16 hi/lo weights, layout [o][k], k = i*8 + s*4 + g
__device__ __nv_bfloat16 g_W1h[32 * 512];
__device__ __nv_bfloat16 g_W1l[32 * 512];
__device__ __nv_bfloat16 g_Wch[2 * 32 * 256];
__device__ __nv_bfloat16 g_Wcl[2 * 32 * 256];

// ---------------- helpers ---------------------------------------------------
__device__ __forceinline__ int ldidx(const void* p, long long i, int is64) {
    if (is64) return (int)__ldg((const long long*)p + i);
    return __ldg((const int*)p + i);
}
__device__ __forceinline__ float lrelu(float v) { return v > 0.f ? v : 0.01f * v; }
__device__ __forceinline__ uint32_t smem_u32(const void* p) {
    uint32_t a;
    asm("{ .reg .u64 t; cvta.to.shared.u64 t, %1; cvt.u32.u64 %0, t; }"
        : "=r"(a) : "l"(p));
    return a;
}
// pack (lo, hi) floats into a bf16x2 word (lo in bits [0,16))
__device__ __forceinline__ uint32_t bfpack(float lo, float hi) {
    uint32_t d;
    asm("cvt.rn.bf16x2.f32 %0, %1, %2;" : "=r"(d) : "f"(hi), "f"(lo));
    return d;
}
__device__ __forceinline__ void ldmatrix_x4(uint32_t* r, uint32_t addr) {
    asm volatile("ldmatrix.sync.aligned.m8n8.x4.shared.b16 {%0,%1,%2,%3}, [%4];"
                 : "=r"(r[0]), "=r"(r[1]), "=r"(r[2]), "=r"(r[3]) : "r"(addr));
}
__device__ __forceinline__ void ldmatrix_x2(uint32_t& r0, uint32_t& r1, uint32_t addr) {
    asm volatile("ldmatrix.sync.aligned.m8n8.x2.shared.b16 {%0,%1}, [%2];"
                 : "=r"(r0), "=r"(r1) : "r"(addr));
}
__device__ __forceinline__ void mma16816(float* d, const uint32_t* a,
                                         uint32_t b0, uint32_t b1) {
    asm volatile("mma.sync.aligned.m16n8k16.row.col.f32.bf16.bf16.f32 "
                 "{%0,%1,%2,%3}, {%4,%5,%6,%7}, {%8,%9}, {%0,%1,%2,%3};"
                 : "+f"(d[0]), "+f"(d[1]), "+f"(d[2]), "+f"(d[3])
                 : "r"(a[0]), "r"(a[1]), "r"(a[2]), "r"(a[3]), "r"(b0), "r"(b1));
}

// ---------------- init: zero pool buffers + detect index dtype --------------
__global__ void k_init(const void* ei) {
    int j = blockIdx.x * blockDim.x + threadIdx.x;
    if (j < NG * HID) g_sums[j] = 0.f;
    if (j < NG) g_cnt[j] = 0.f;
    if (j == 0) {
        const unsigned* a = (const unsigned*)ei;
        int is64 = 1;
        for (int i = 0; i < 32; i++)
            if (a[2 * i + 1] != 0u) is64 = 0;
        g_is64 = is64;
    }
}

// ---------------- weight prep: rearrange + bf16 hi/lo split ------------------
// k-order: k = i*8 + s*4 + g  (s=0 cos, s=1 sin; harmonic multiplier g+1)
__global__ void k_prep(const float* __restrict__ W_in, const float* __restrict__ W_conv) {
    int j = blockIdx.x * blockDim.x + threadIdx.x;
    float w; int dst;
    __nv_bfloat16 *Dh, *Dl;
    if (j < 16384) {                     // W_in (2,32,64,4)
        int g = j & 3, i = (j >> 2) & 63, o = (j >> 8) & 31, s = j >> 13;
        w = W_in[j];
        dst = o * 512 + i * 8 + s * 4 + g;
        Dh = g_W1h; Dl = g_W1l;
    } else if (j < 32768) {              // W_conv (2,2,32,32,4)
        int jj = j - 16384;
        int l = jj >> 13;
        int r = jj & 8191;
        int g = r & 3, i = (r >> 2) & 31, o = (r >> 7) & 31, s = r >> 12;
        w = W_conv[jj];
        dst = o * 256 + i * 8 + s * 4 + g;
        Dh = g_Wch + l * 8192; Dl = g_Wcl + l * 8192;
    } else return;
    __nv_bfloat16 h = __float2bfloat16(w);
    Dh[dst] = h;
    Dl[dst] = __float2bfloat16(w - __bfloat162float(h));
}

// ---------------- KAN layer via warp-level bf16 MMA (mma.sync) ---------------
// Y[n,o] = sum_k Phi[n,k]*W[o,k]; Phi = [cos((g+1)x), sin((g+1)x)], k=i*8+s*4+g.
// bf16 3-term split: D = Ph*Wh + Ph*Wl + Pl*Wh, fp32 accumulate.
// Block = 256 thr = 8 warps; warp w owns node rows [blk*128+16w, +16) x all 32 o.
// Phi staged per 32-k chunk (4 inputs) in a tiny per-warp smem buffer
// (16 rows x 64B, pitch 80B -> ldmatrix conflict-free). This keeps total smem
// at 53KB (conv) / 86KB (layer1) so 4 / 2 CTAs per SM (R7 was occupancy-bound
// at 102/135KB).
// Weight smem tile: row (kt*32+o) of 32B = W[o][16 k]; plain ldmatrix.x2 of
// these rows yields the col-major B fragment directly.
// MODE 0: in = x,            out = g_h
// MODE 1: in = g_h,          out = g_T, zero g_acc
// MODE 2: in = lrelu(acc+h)  (writes h back), out = g_T, zero g_acc
template <int IN, int MODE>
__global__ __launch_bounds__(256) void k_kan_mma(const float* __restrict__ xin, int layer) {
    constexpr int K = IN * 8;
    constexpr int NCH = IN / 4;             // 32-k chunks (4 inputs each)
    constexpr int WBYTES = K * 64;          // weight tile bytes (one of hi/lo)
    constexpr int PH_PITCH = 80;            // 64B row + 16B pad (20 words)
    constexpr int PH_WARP = 16 * PH_PITCH;  // 1280B per warp
    extern __shared__ char smem[];
    const uint32_t SB = smem_u32(smem);
    const uint32_t SM_WH = 0, SM_WL = WBYTES, SM_PH = 2 * WBYTES,
                   SM_PL = SM_PH + 8 * PH_WARP;

    int tid = threadIdx.x;
    int w = tid >> 5, lane = tid & 31;

    // ---- stage weights (permuted 32-bit word copy) ----
    const __nv_bfloat16* Wh = (MODE == 0) ? g_W1h : (g_Wch + layer * 8192);
    const __nv_bfloat16* Wl = (MODE == 0) ? g_W1l : (g_Wcl + layer * 8192);
    const uint32_t* WhU = (const uint32_t*)Wh;
    const uint32_t* WlU = (const uint32_t*)Wl;
    uint32_t* swh = (uint32_t*)(smem + SM_WH);
    uint32_t* swl = (uint32_t*)(smem + SM_WL);
    for (int wdx = tid; wdx < K * 16; wdx += 256) {
        int kt = wdx >> 8;                  // 256 words per k16-tile
        int o = (wdx >> 3) & 31;
        int seg = wdx & 7;
        int src = (o * K + kt * 16 + seg * 2) >> 1;
        int dst = (kt * 32 + o) * 8 + seg;
        swh[dst] = WhU[src];
        swl[dst] = WlU[src];
    }
    __syncthreads();

    // ---- per-lane constant addresses ----
    int nloc = lane & 15, half = lane >> 4;
    int node = blockIdx.x * 128 + w * 16 + nloc;
    int nodeC = node < N_NODES ? node : N_NODES - 1;
    bool nvalid = node < N_NODES;
    // Phi store base for this lane's row (this lane writes inputs half*2..+1)
    uint32_t phiRowH = SB + SM_PH + w * PH_WARP + nloc * PH_PITCH + half * 32;
    uint32_t phiRowL = SB + SM_PL + w * PH_WARP + nloc * PH_PITCH + half * 32;
    // A-ldmatrix address for this lane
    int ar = (lane & 7) + (lane & 8);
    uint32_t aBaseH = SB + SM_PH + w * PH_WARP + ar * PH_PITCH + (lane >> 4) * 16;
    uint32_t aBaseL = SB + SM_PL + w * PH_WARP + ar * PH_PITCH + (lane >> 4) * 16;
    // B-ldmatrix per-lane offset (lanes 0-15 meaningful)
    uint32_t bLane = (uint32_t)((lane & 7) * 32 + ((lane >> 3) & 1) * 16);

    float acc[4][4];
#pragma unroll
    for (int nt = 0; nt < 4; nt++)
#pragma unroll
        for (int j = 0; j < 4; j++) acc[nt][j] = 0.f;

#pragma unroll 1
    for (int c = 0; c < NCH; c++) {
        // ---- compute Phi chunk (4 inputs) for this warp's 16 rows ----
        int ibase = c * 4 + half * 2;       // this lane: inputs ibase, ibase+1
        float xv[2];
        if (MODE == 0) {
            const float2* xp = (const float2*)(xin + (size_t)nodeC * IN + ibase);
            float2 a = __ldg(xp);
            xv[0] = a.x; xv[1] = a.y;
        } else if (MODE == 1) {
            float2 a = *(const float2*)(g_h + nodeC * HID + ibase);
            xv[0] = a.x; xv[1] = a.y;
        } else {
            float2* hp = (float2*)(g_h + nodeC * HID + ibase);
            const float2* ap = (const float2*)(g_acc + nodeC * HID + ibase);
            float2 m = *ap, h = *hp;
            float2 r;
            r.x = lrelu(m.x + h.x); r.y = lrelu(m.y + h.y);
            if (nvalid) *hp = r;            // h_{l+1} writeback (one lane/elem)
            xv[0] = r.x; xv[1] = r.y;
        }
#pragma unroll
        for (int u = 0; u < 2; u++) {
            float s1, c1;
            __sincosf(xv[u], &s1, &c1);
            float t2 = c1 + c1;
            float c2 = fmaf(t2, c1, -1.f), s2 = t2 * s1;
            float c3 = fmaf(t2, c2, -c1),  s3 = fmaf(t2, s2, -s1);
            float c4 = fmaf(t2, c3, -c2),  s4 = fmaf(t2, s3, -s2);
            float v[8] = { c1, c2, c3, c4, s1, s2, s3, s4 };
            uint32_t hw[4], lw[4];
#pragma unroll
            for (int j = 0; j < 4; j++) {
                hw[j] = bfpack(v[2 * j], v[2 * j + 1]);
                float r0 = v[2 * j]     - __uint_as_float(hw[j] << 16);
                float r1 = v[2 * j + 1] - __uint_as_float(hw[j] & 0xFFFF0000u);
                lw[j] = bfpack(r0, r1);
            }
            asm volatile("st.shared.v4.b32 [%0], {%1,%2,%3,%4};"
                         :: "r"(phiRowH + u * 16), "r"(hw[0]), "r"(hw[1]), "r"(hw[2]), "r"(hw[3]) : "memory");
            asm volatile("st.shared.v4.b32 [%0], {%1,%2,%3,%4};"
                         :: "r"(phiRowL + u * 16), "r"(lw[0]), "r"(lw[1]), "r"(lw[2]), "r"(lw[3]) : "memory");
        }
        __syncwarp();

        // ---- MMA over this chunk: 2 k16 steps ----
#pragma unroll
        for (int kk = 0; kk < 2; kk++) {
            uint32_t ah[4], al[4];
            ldmatrix_x4(ah, aBaseH + kk * 32);
            ldmatrix_x4(al, aBaseL + kk * 32);
            uint32_t bt = SB + (uint32_t)((c * 2 + kk) * 1024) + bLane;
#pragma unroll
            for (int nt = 0; nt < 4; nt++) {
                uint32_t bh0, bh1, bl0, bl1;
                ldmatrix_x2(bh0, bh1, SM_WH + bt + nt * 256);
                ldmatrix_x2(bl0, bl1, SM_WL + bt + nt * 256);
                mma16816(acc[nt], ah, bh0, bh1);
                mma16816(acc[nt], ah, bl0, bl1);
                mma16816(acc[nt], al, bh0, bh1);
            }
        }
        __syncwarp();   // before next chunk overwrites Phi
    }

    // ---- write D ----
    float* outbase = (MODE == 0) ? g_h : g_T;
    int gq = lane >> 2, tg = lane & 3;
    int row0 = blockIdx.x * 128 + w * 16 + gq;
    int row1 = row0 + 8;
    if (row0 < N_NODES) {
        float* p = outbase + row0 * HID + 2 * tg;
#pragma unroll
        for (int nt = 0; nt < 4; nt++)
            *(float2*)(p + nt * 8) = make_float2(acc[nt][0], acc[nt][1]);
    }
    if (row1 < N_NODES) {
        float* p = outbase + row1 * HID + 2 * tg;
#pragma unroll
        for (int nt = 0; nt < 4; nt++)
            *(float2*)(p + nt * 8) = make_float2(acc[nt][2], acc[nt][3]);
    }
    if (MODE != 0 && nvalid) {   // zero scatter buffer (each lane: half a row)
        float4 z = make_float4(0.f, 0.f, 0.f, 0.f);
        float4* az = (float4*)(g_acc + node * HID + half * 16);
        az[0] = z; az[1] = z;
        az[2] = z; az[3] = z;
    }
}

// ---------------- edge scatter: acc[dst] += T[src] --------------------------
__global__ void k_scatter(const void* __restrict__ ei, int E) {
    long long gid = (long long)blockIdx.x * blockDim.x + threadIdx.x;
    int e = (int)(gid >> 3);
    int q = (int)(gid & 7);
    if (e >= E) return;
    int is64 = g_is64;
    int src = ldidx(ei, e, is64);
    int dst = ldidx(ei, (long long)E + e, is64);
    float4 v = __ldg((const float4*)g_T + src * (HID / 4) + q);
    float* p = g_acc + dst * HID + q * 4;
    asm volatile("red.global.add.v4.f32 [%0], {%1, %2, %3, %4};"
                 :: "l"(p), "f"(v.x), "f"(v.y), "f"(v.z), "f"(v.w)
                 : "memory");
}

// ---------------- pooling (fused final leaky-relu + residual) ---------------
__global__ void k_pool(const void* __restrict__ batch) {
    int warp = (blockIdx.x * blockDim.x + threadIdx.x) >> 5;
    int lane = threadIdx.x & 31;
    if (warp >= N_NODES) return;
    int b = ldidx(batch, warp, g_is64);
    float m = g_acc[warp * HID + lane];
    float h = g_h[warp * HID + lane];
    float v = lrelu(m + h);
    atomicAdd(&g_sums[b * HID + lane], v);
    if (lane == 0) atomicAdd(&g_cnt[b], 1.f);
}

// ---------------- readout: sigmoid(KAN_linear(mean_pool)) -------------------
__global__ void k_readout(const float* __restrict__ Wout,
                          const float* __restrict__ bout,
                          float* __restrict__ out) {
    int g = threadIdx.x;
    if (g >= NG) return;
    float cnt = fmaxf(g_cnt[g], 1.f);
    float inv = 1.f / cnt;
    float acc = 0.f;
#pragma unroll
    for (int c = 0; c < HID; c++) {
        float y = g_sums[g * HID + c] * inv;
        float s, co;
        __sincosf(y, &s, &co);
        acc = fmaf(co, Wout[c], acc);
        acc = fmaf(s, Wout[HID + c], acc);
    }
    acc += bout[0];
    out[g] = 1.f / (1.f + __expf(-acc));
}

// ---------------- launch ----------------------------------------------------
extern "C" void kernel_launch(void* const* d_in, const int* in_sizes, int n_in,
                              void* d_out, int out_size) {
    const float* x      = (const float*)d_in[0];
    const void*  ei     = d_in[1];
    const void*  batch  = d_in[2];
    const float* W_in   = (const float*)d_in[3];
    const float* W_conv = (const float*)d_in[4];
    const float* W_out  = (const float*)d_in[5];
    const float* b_out  = (const float*)d_in[6];
    float* out = (float*)d_out;

    int E = in_sizes[1] / 2;

    const int SM1 = 2 * 512 * 64 + 2 * 8 * 1280;   // 65536 + 20480 = 86016
    const int SMC = 2 * 256 * 64 + 2 * 8 * 1280;   // 32768 + 20480 = 53248
    cudaFuncSetAttribute(k_kan_mma<IN_FEAT, 0>, cudaFuncAttributeMaxDynamicSharedMemorySize, SM1);
    cudaFuncSetAttribute(k_kan_mma<HID, 1>,     cudaFuncAttributeMaxDynamicSharedMemorySize, SMC);
    cudaFuncSetAttribute(k_kan_mma<HID, 2>,     cudaFuncAttributeMaxDynamicSharedMemorySize, SMC);

    k_init<<<16, 256>>>(ei);
    k_prep<<<128, 256>>>(W_in, W_conv);

    int nb = (N_NODES + 127) / 128;        // 391 tiles of 128 nodes
    long long tthreads = (long long)E * 8;
    int sb = (int)((tthreads + 255) / 256);

    k_kan_mma<IN_FEAT, 0><<<nb, 256, SM1>>>(x, 0);

    k_kan_mma<HID, 1><<<nb, 256, SMC>>>(nullptr, 0);
    k_scatter<<<sb, 256>>>(ei, E);

    k_kan_mma<HID, 2><<<nb, 256, SMC>>>(nullptr, 1);
    k_scatter<<<sb, 256>>>(ei, E);

    k_pool<<<(N_NODES + 7) / 8, 256>>>(batch);
    k_readout<<<1, 128>>>(W_out, b_out, out);
}

// round 9
// speedup vs baseline: 1.0952x; 1.0952x over previous
#include <cuda_runtime.h>
#include <cuda_bf16.h>
#include <cstdint>

#define N_NODES 50000
#define IN_FEAT 64
#define HID 32
#define NG 128

// ---------------- scratch (static device globals; no allocs allowed) --------
__device__ float g_h[N_NODES * HID];
__device__ float g_T[N_NODES * HID];
__device__ float g_acc[N_NODES * HID];
__device__ float g_sums[NG * HID];
__device__ float g_cnt[NG];
__device__ int   g_is64;
// prepped bf16 hi/lo weights, layout [o][k], k = i*8 + s*4 + g
__device__ __nv_bfloat16 g_W1h[32 * 512];
__device__ __nv_bfloat16 g_W1l[32 * 512];
__device__ __nv_bfloat16 g_Wch[2 * 32 * 256];
__device__ __nv_bfloat16 g_Wcl[2 * 32 * 256];

// ---------------- helpers ---------------------------------------------------
__device__ __forceinline__ int ldidx(const void* p, long long i, int is64) {
    if (is64) return (int)__ldg((const long long*)p + i);
    return __ldg((const int*)p + i);
}
__device__ __forceinline__ float lrelu(float v) { return v > 0.f ? v : 0.01f * v; }
__device__ __forceinline__ uint32_t smem_u32(const void* p) {
    uint32_t a;
    asm("{ .reg .u64 t; cvta.to.shared.u64 t, %1; cvt.u32.u64 %0, t; }"
        : "=r"(a) : "l"(p));
    return a;
}
// pack (lo, hi) floats into a bf16x2 word (lo in bits [0,16))
__device__ __forceinline__ uint32_t bfpack(float lo, float hi) {
    uint32_t d;
    asm("cvt.rn.bf16x2.f32 %0, %1, %2;" : "=r"(d) : "f"(hi), "f"(lo));
    return d;
}
__device__ __forceinline__ void ldmatrix_x4(uint32_t* r, uint32_t addr) {
    asm volatile("ldmatrix.sync.aligned.m8n8.x4.shared.b16 {%0,%1,%2,%3}, [%4];"
                 : "=r"(r[0]), "=r"(r[1]), "=r"(r[2]), "=r"(r[3]) : "r"(addr));
}
__device__ __forceinline__ void ldmatrix_x2(uint32_t& r0, uint32_t& r1, uint32_t addr) {
    asm volatile("ldmatrix.sync.aligned.m8n8.x2.shared.b16 {%0,%1}, [%2];"
                 : "=r"(r0), "=r"(r1) : "r"(addr));
}
__device__ __forceinline__ void mma16816(float* d, const uint32_t* a,
                                         uint32_t b0, uint32_t b1) {
    asm volatile("mma.sync.aligned.m16n8k16.row.col.f32.bf16.bf16.f32 "
                 "{%0,%1,%2,%3}, {%4,%5,%6,%7}, {%8,%9}, {%0,%1,%2,%3};"
                 : "+f"(d[0]), "+f"(d[1]), "+f"(d[2]), "+f"(d[3])
                 : "r"(a[0]), "r"(a[1]), "r"(a[2]), "r"(a[3]), "r"(b0), "r"(b1));
}

// ---------------- init: zero pool buffers + detect index dtype --------------
__global__ void k_init(const void* ei) {
    int j = blockIdx.x * blockDim.x + threadIdx.x;
    if (j < NG * HID) g_sums[j] = 0.f;
    if (j < NG) g_cnt[j] = 0.f;
    if (j == 0) {
        const unsigned* a = (const unsigned*)ei;
        int is64 = 1;
        for (int i = 0; i < 32; i++)
            if (a[2 * i + 1] != 0u) is64 = 0;
        g_is64 = is64;
    }
}

// ---------------- weight prep: rearrange + bf16 hi/lo split ------------------
// k-order: k = i*8 + s*4 + g  (s=0 cos, s=1 sin; harmonic multiplier g+1)
__global__ void k_prep(const float* __restrict__ W_in, const float* __restrict__ W_conv) {
    int j = blockIdx.x * blockDim.x + threadIdx.x;
    float w; int dst;
    __nv_bfloat16 *Dh, *Dl;
    if (j < 16384) {                     // W_in (2,32,64,4)
        int g = j & 3, i = (j >> 2) & 63, o = (j >> 8) & 31, s = j >> 13;
        w = W_in[j];
        dst = o * 512 + i * 8 + s * 4 + g;
        Dh = g_W1h; Dl = g_W1l;
    } else if (j < 32768) {              // W_conv (2,2,32,32,4)
        int jj = j - 16384;
        int l = jj >> 13;
        int r = jj & 8191;
        int g = r & 3, i = (r >> 2) & 31, o = (r >> 7) & 31, s = r >> 12;
        w = W_conv[jj];
        dst = o * 256 + i * 8 + s * 4 + g;
        Dh = g_Wch + l * 8192; Dl = g_Wcl + l * 8192;
    } else return;
    __nv_bfloat16 h = __float2bfloat16(w);
    Dh[dst] = h;
    Dl[dst] = __float2bfloat16(w - __bfloat162float(h));
}

// ---------------- KAN layer via warp-level bf16 MMA (mma.sync) ---------------
// Y[n,o] = sum_k Phi[n,k]*W[o,k]; Phi = [cos((g+1)x), sin((g+1)x)], k=i*8+s*4+g.
// bf16 3-term split: D = Ph*Wh + Ph*Wl + Pl*Wh, fp32 accumulate.
// Block = 256 thr = 8 warps; warp w owns 32 node rows (2 m16 row-groups) x all
// 32 outputs -> B-fragment ldmatrix amortized over 2x MMA vs R8 (which was
// L1/LDS-pipe-bound at 60% L1, 19% issue).
// Lane L owns row L of its warp entirely: per 32-k chunk it loads ONE float4
// of inputs, computes 4 sincos + Chebyshev, stores the row's 64B hi + lo Phi.
// MODE-2 h-writeback / g_acc zeroing therefore touch each element from exactly
// one lane (race-free by construction).
// Phi smem: per warp 32 rows x 80B (64B data + 16B pad; conflict-free for
// STS.128 and ldmatrix within each 8-lane phase), hi and lo planes.
// Weight smem tile: row (kt*32+o) of 32B = W[o][16 k]; ldmatrix.x2 of these
// rows yields the col-major B fragment directly (validated R7/R8).
// MODE 0: in = x,            out = g_h
// MODE 1: in = g_h,          out = g_T, zero g_acc
// MODE 2: in = lrelu(acc+h)  (writes h back), out = g_T, zero g_acc
template <int IN, int MODE>
__global__ __launch_bounds__(256) void k_kan_mma(const float* __restrict__ xin, int layer) {
    constexpr int K = IN * 8;
    constexpr int NCH = IN / 4;             // 32-k chunks (4 inputs each)
    constexpr int WBYTES = K * 64;          // weight tile bytes (one of hi/lo)
    constexpr int PH_PITCH = 80;            // 64B row + 16B pad
    constexpr int PH_WARP = 32 * PH_PITCH;  // 2560B per warp per plane
    extern __shared__ char smem[];
    const uint32_t SB = smem_u32(smem);
    const uint32_t SM_WH = 0, SM_WL = WBYTES, SM_PH = 2 * WBYTES,
                   SM_PL = SM_PH + 8 * PH_WARP;

    int tid = threadIdx.x;
    int w = tid >> 5, lane = tid & 31;

    // ---- stage weights (permuted 32-bit word copy) ----
    const __nv_bfloat16* Wh = (MODE == 0) ? g_W1h : (g_Wch + layer * 8192);
    const __nv_bfloat16* Wl = (MODE == 0) ? g_W1l : (g_Wcl + layer * 8192);
    const uint32_t* WhU = (const uint32_t*)Wh;
    const uint32_t* WlU = (const uint32_t*)Wl;
    uint32_t* swh = (uint32_t*)(smem + SM_WH);
    uint32_t* swl = (uint32_t*)(smem + SM_WL);
    for (int wdx = tid; wdx < K * 16; wdx += 256) {
        int kt = wdx >> 8;                  // 256 words per k16-tile
        int o = (wdx >> 3) & 31;
        int seg = wdx & 7;
        int src = (o * K + kt * 16 + seg * 2) >> 1;
        int dst = (kt * 32 + o) * 8 + seg;
        swh[dst] = WhU[src];
        swl[dst] = WlU[src];
    }
    __syncthreads();

    // ---- per-lane constant addresses ----
    int node = blockIdx.x * 256 + w * 32 + lane;
    int nodeC = node < N_NODES ? node : N_NODES - 1;
    bool nvalid = node < N_NODES;
    uint32_t phiRowH = SB + SM_PH + w * PH_WARP + lane * PH_PITCH;
    uint32_t phiRowL = SB + SM_PL + w * PH_WARP + lane * PH_PITCH;
    // A-ldmatrix address (row-group 0; group 1 at +16*80)
    int ar = (lane & 7) + (lane & 8);
    uint32_t aBaseH = SB + SM_PH + w * PH_WARP + ar * PH_PITCH + (lane >> 4) * 16;
    uint32_t aBaseL = SB + SM_PL + w * PH_WARP + ar * PH_PITCH + (lane >> 4) * 16;
    // B-ldmatrix per-lane offset (lanes 0-15 meaningful)
    uint32_t bLane = (uint32_t)((lane & 7) * 32 + ((lane >> 3) & 1) * 16);

    float acc[2][4][4];
#pragma unroll
    for (int gp = 0; gp < 2; gp++)
#pragma unroll
        for (int nt = 0; nt < 4; nt++)
#pragma unroll
            for (int j = 0; j < 4; j++) acc[gp][nt][j] = 0.f;

#pragma unroll 1
    for (int c = 0; c < NCH; c++) {
        // ---- Phi chunk: lane computes its own row, inputs c*4 .. c*4+3 ----
        float4 xv4;
        if (MODE == 0) {
            xv4 = __ldg((const float4*)(xin + (size_t)nodeC * IN + c * 4));
        } else if (MODE == 1) {
            xv4 = *(const float4*)(g_h + nodeC * HID + c * 4);
        } else {
            float4* hp = (float4*)(g_h + nodeC * HID + c * 4);
            const float4* ap = (const float4*)(g_acc + nodeC * HID + c * 4);
            float4 m = *ap, h = *hp;
            xv4.x = lrelu(m.x + h.x); xv4.y = lrelu(m.y + h.y);
            xv4.z = lrelu(m.z + h.z); xv4.w = lrelu(m.w + h.w);
            if (nvalid) *hp = xv4;          // h_{l+1} writeback (exclusive lane)
        }
#pragma unroll
        for (int u = 0; u < 4; u++) {
            float xv = (&xv4.x)[u];
            float s1, c1;
            __sincosf(xv, &s1, &c1);
            float t2 = c1 + c1;
            float c2 = fmaf(t2, c1, -1.f), s2 = t2 * s1;
            float c3 = fmaf(t2, c2, -c1),  s3 = fmaf(t2, s2, -s1);
            float c4 = fmaf(t2, c3, -c2),  s4 = fmaf(t2, s3, -s2);
            float v[8] = { c1, c2, c3, c4, s1, s2, s3, s4 };
            uint32_t hw[4], lw[4];
#pragma unroll
            for (int j = 0; j < 4; j++) {
                hw[j] = bfpack(v[2 * j], v[2 * j + 1]);
                float r0 = v[2 * j]     - __uint_as_float(hw[j] << 16);
                float r1 = v[2 * j + 1] - __uint_as_float(hw[j] & 0xFFFF0000u);
                lw[j] = bfpack(r0, r1);
            }
            asm volatile("st.shared.v4.b32 [%0], {%1,%2,%3,%4};"
                         :: "r"(phiRowH + u * 16), "r"(hw[0]), "r"(hw[1]), "r"(hw[2]), "r"(hw[3]) : "memory");
            asm volatile("st.shared.v4.b32 [%0], {%1,%2,%3,%4};"
                         :: "r"(phiRowL + u * 16), "r"(lw[0]), "r"(lw[1]), "r"(lw[2]), "r"(lw[3]) : "memory");
        }
        __syncwarp();

        // ---- MMA over this chunk: 2 k16 steps, 2 row-groups ----
#pragma unroll
        for (int kk = 0; kk < 2; kk++) {
            uint32_t ah0[4], ah1[4], al0[4], al1[4];
            ldmatrix_x4(ah0, aBaseH + kk * 32);
            ldmatrix_x4(ah1, aBaseH + 16 * PH_PITCH + kk * 32);
            ldmatrix_x4(al0, aBaseL + kk * 32);
            ldmatrix_x4(al1, aBaseL + 16 * PH_PITCH + kk * 32);
            uint32_t bt = SB + (uint32_t)((c * 2 + kk) * 1024) + bLane;
#pragma unroll
            for (int nt = 0; nt < 4; nt++) {
                uint32_t bh0, bh1, bl0, bl1;
                ldmatrix_x2(bh0, bh1, SM_WH + bt + nt * 256);
                ldmatrix_x2(bl0, bl1, SM_WL + bt + nt * 256);
                mma16816(acc[0][nt], ah0, bh0, bh1);
                mma16816(acc[0][nt], ah0, bl0, bl1);
                mma16816(acc[0][nt], al0, bh0, bh1);
                mma16816(acc[1][nt], ah1, bh0, bh1);
                mma16816(acc[1][nt], ah1, bl0, bl1);
                mma16816(acc[1][nt], al1, bh0, bh1);
            }
        }
        __syncwarp();   // before next chunk overwrites Phi
    }

    // ---- write D ----
    float* outbase = (MODE == 0) ? g_h : g_T;
    int gq = lane >> 2, tg = lane & 3;
#pragma unroll
    for (int gp = 0; gp < 2; gp++) {
        int row0 = blockIdx.x * 256 + w * 32 + gp * 16 + gq;
        int row1 = row0 + 8;
        if (row0 < N_NODES) {
            float* p = outbase + row0 * HID + 2 * tg;
#pragma unroll
            for (int nt = 0; nt < 4; nt++)
                *(float2*)(p + nt * 8) = make_float2(acc[gp][nt][0], acc[gp][nt][1]);
        }
        if (row1 < N_NODES) {
            float* p = outbase + row1 * HID + 2 * tg;
#pragma unroll
            for (int nt = 0; nt < 4; nt++)
                *(float2*)(p + nt * 8) = make_float2(acc[gp][nt][2], acc[gp][nt][3]);
        }
    }
    if (MODE != 0 && nvalid) {   // zero scatter buffer row (exclusive lane)
        float4 z = make_float4(0.f, 0.f, 0.f, 0.f);
        float4* az = (float4*)(g_acc + node * HID);
#pragma unroll
        for (int j = 0; j < 8; j++) az[j] = z;
    }
}

// ---------------- edge scatter: acc[dst] += T[src] --------------------------
__global__ void k_scatter(const void* __restrict__ ei, int E) {
    long long gid = (long long)blockIdx.x * blockDim.x + threadIdx.x;
    int e = (int)(gid >> 3);
    int q = (int)(gid & 7);
    if (e >= E) return;
    int is64 = g_is64;
    int src = ldidx(ei, e, is64);
    int dst = ldidx(ei, (long long)E + e, is64);
    float4 v = __ldg((const float4*)g_T + src * (HID / 4) + q);
    float* p = g_acc + dst * HID + q * 4;
    asm volatile("red.global.add.v4.f32 [%0], {%1, %2, %3, %4};"
                 :: "l"(p), "f"(v.x), "f"(v.y), "f"(v.z), "f"(v.w)
                 : "memory");
}

// ---------------- pooling (fused final leaky-relu + residual) ---------------
__global__ void k_pool(const void* __restrict__ batch) {
    int warp = (blockIdx.x * blockDim.x + threadIdx.x) >> 5;
    int lane = threadIdx.x & 31;
    if (warp >= N_NODES) return;
    int b = ldidx(batch, warp, g_is64);
    float m = g_acc[warp * HID + lane];
    float h = g_h[warp * HID + lane];
    float v = lrelu(m + h);
    atomicAdd(&g_sums[b * HID + lane], v);
    if (lane == 0) atomicAdd(&g_cnt[b], 1.f);
}

// ---------------- readout: sigmoid(KAN_linear(mean_pool)) -------------------
__global__ void k_readout(const float* __restrict__ Wout,
                          const float* __restrict__ bout,
                          float* __restrict__ out) {
    int g = threadIdx.x;
    if (g >= NG) return;
    float cnt = fmaxf(g_cnt[g], 1.f);
    float inv = 1.f / cnt;
    float acc = 0.f;
#pragma unroll
    for (int c = 0; c < HID; c++) {
        float y = g_sums[g * HID + c] * inv;
        float s, co;
        __sincosf(y, &s, &co);
        acc = fmaf(co, Wout[c], acc);
        acc = fmaf(s, Wout[HID + c], acc);
    }
    acc += bout[0];
    out[g] = 1.f / (1.f + __expf(-acc));
}

// ---------------- launch ----------------------------------------------------
extern "C" void kernel_launch(void* const* d_in, const int* in_sizes, int n_in,
                              void* d_out, int out_size) {
    const float* x      = (const float*)d_in[0];
    const void*  ei     = d_in[1];
    const void*  batch  = d_in[2];
    const float* W_in   = (const float*)d_in[3];
    const float* W_conv = (const float*)d_in[4];
    const float* W_out  = (const float*)d_in[5];
    const float* b_out  = (const float*)d_in[6];
    float* out = (float*)d_out;

    int E = in_sizes[1] / 2;

    const int SM1 = 2 * 512 * 64 + 2 * 8 * 2560;   // 65536 + 40960 = 106496
    const int SMC = 2 * 256 * 64 + 2 * 8 * 2560;   // 32768 + 40960 = 73728
    cudaFuncSetAttribute(k_kan_mma<IN_FEAT, 0>, cudaFuncAttributeMaxDynamicSharedMemorySize, SM1);
    cudaFuncSetAttribute(k_kan_mma<HID, 1>,     cudaFuncAttributeMaxDynamicSharedMemorySize, SMC);
    cudaFuncSetAttribute(k_kan_mma<HID, 2>,     cudaFuncAttributeMaxDynamicSharedMemorySize, SMC);

    k_init<<<16, 256>>>(ei);
    k_prep<<<128, 256>>>(W_in, W_conv);

    int nb = (N_NODES + 255) / 256;        // 196 tiles of 256 nodes
    long long tthreads = (long long)E * 8;
    int sb = (int)((tthreads + 255) / 256);

    k_kan_mma<IN_FEAT, 0><<<nb, 256, SM1>>>(x, 0);

    k_kan_mma<HID, 1><<<nb, 256, SMC>>>(nullptr, 0);
    k_scatter<<<sb, 256>>>(ei, E);

    k_kan_mma<HID, 2><<<nb, 256, SMC>>>(nullptr, 1);
    k_scatter<<<sb, 256>>>(ei, E);

    k_pool<<<(N_NODES + 7) / 8, 256>>>(batch);
    k_readout<<<1, 128>>>(W_out, b_out, out);
}

// round 10
// speedup vs baseline: 1.1132x; 1.0164x over previous
#include <cuda_runtime.h>
#include <cuda_bf16.h>
#include <cstdint>

#define N_NODES 50000
#define IN_FEAT 64
#define HID 32
#define NG 128

// ---------------- scratch (static device globals; no allocs allowed) --------
__device__ float g_h[N_NODES * HID];
__device__ float g_T[N_NODES * HID];
__device__ float g_acc[N_NODES * HID];
__device__ float g_sums[NG * HID];
__device__ float g_cnt[NG];
__device__ int   g_is64;
// prepped bf16 hi/lo weights, layout [o][k], k = i*8 + s*4 + g
__device__ __nv_bfloat16 g_W1h[32 * 512];
__device__ __nv_bfloat16 g_W1l[32 * 512];
__device__ __nv_bfloat16 g_Wch[2 * 32 * 256];
__device__ __nv_bfloat16 g_Wcl[2 * 32 * 256];

// ---------------- helpers ---------------------------------------------------
__device__ __forceinline__ int ldidx(const void* p, long long i, int is64) {
    if (is64) return (int)__ldg((const long long*)p + i);
    return __ldg((const int*)p + i);
}
__device__ __forceinline__ float lrelu(float v) { return v > 0.f ? v : 0.01f * v; }
__device__ __forceinline__ uint32_t smem_u32(const void* p) {
    uint32_t a;
    asm("{ .reg .u64 t; cvta.to.shared.u64 t, %1; cvt.u32.u64 %0, t; }"
        : "=r"(a) : "l"(p));
    return a;
}
// pack (lo, hi) floats into a bf16x2 word (lo in bits [0,16))
__device__ __forceinline__ uint32_t bfpack(float lo, float hi) {
    uint32_t d;
    asm("cvt.rn.bf16x2.f32 %0, %1, %2;" : "=r"(d) : "f"(hi), "f"(lo));
    return d;
}
__device__ __forceinline__ void ldmatrix_x4(uint32_t* r, uint32_t addr) {
    asm volatile("ldmatrix.sync.aligned.m8n8.x4.shared.b16 {%0,%1,%2,%3}, [%4];"
                 : "=r"(r[0]), "=r"(r[1]), "=r"(r[2]), "=r"(r[3]) : "r"(addr));
}
__device__ __forceinline__ void mma16816(float* d, const uint32_t* a,
                                         uint32_t b0, uint32_t b1) {
    asm volatile("mma.sync.aligned.m16n8k16.row.col.f32.bf16.bf16.f32 "
                 "{%0,%1,%2,%3}, {%4,%5,%6,%7}, {%8,%9}, {%0,%1,%2,%3};"
                 : "+f"(d[0]), "+f"(d[1]), "+f"(d[2]), "+f"(d[3])
                 : "r"(a[0]), "r"(a[1]), "r"(a[2]), "r"(a[3]), "r"(b0), "r"(b1));
}

// ---------------- init: zero pool buffers + detect index dtype --------------
__global__ void k_init(const void* ei) {
    int j = blockIdx.x * blockDim.x + threadIdx.x;
    if (j < NG * HID) g_sums[j] = 0.f;
    if (j < NG) g_cnt[j] = 0.f;
    if (j == 0) {
        const unsigned* a = (const unsigned*)ei;
        int is64 = 1;
        for (int i = 0; i < 32; i++)
            if (a[2 * i + 1] != 0u) is64 = 0;
        g_is64 = is64;
    }
}

// ---------------- weight prep: rearrange + bf16 hi/lo split ------------------
// k-order: k = i*8 + s*4 + g  (s=0 cos, s=1 sin; harmonic multiplier g+1)
__global__ void k_prep(const float* __restrict__ W_in, const float* __restrict__ W_conv) {
    int j = blockIdx.x * blockDim.x + threadIdx.x;
    float w; int dst;
    __nv_bfloat16 *Dh, *Dl;
    if (j < 16384) {                     // W_in (2,32,64,4)
        int g = j & 3, i = (j >> 2) & 63, o = (j >> 8) & 31, s = j >> 13;
        w = W_in[j];
        dst = o * 512 + i * 8 + s * 4 + g;
        Dh = g_W1h; Dl = g_W1l;
    } else if (j < 32768) {              // W_conv (2,2,32,32,4)
        int jj = j - 16384;
        int l = jj >> 13;
        int r = jj & 8191;
        int g = r & 3, i = (r >> 2) & 31, o = (r >> 7) & 31, s = r >> 12;
        w = W_conv[jj];
        dst = o * 256 + i * 8 + s * 4 + g;
        Dh = g_Wch + l * 8192; Dl = g_Wcl + l * 8192;
    } else return;
    __nv_bfloat16 h = __float2bfloat16(w);
    Dh[dst] = h;
    Dl[dst] = __float2bfloat16(w - __bfloat162float(h));
}

// ---------------- KAN layer via warp-level bf16 MMA (mma.sync) ---------------
// Y[n,o] = sum_k Phi[n,k]*W[o,k]; Phi = [cos((g+1)x), sin((g+1)x)], k=i*8+s*4+g.
// bf16 3-term split: D = Ph*Wh + Ph*Wl + Pl*Wh, fp32 accumulate.
// Block = 128 thr = 4 warps (grid 391 -> ~2.6 CTAs/SM; R9's 196-block grid
// wave-quantized at 1.32 waves). Warp owns 32 node rows x all 32 outputs;
// lane L owns row L entirely (race-free MODE-2 writeback).
// SW pipeline: double-buffered Phi; iteration c issues ldmatrix for chunk c,
// then computes chunk c+1's trig into the other buffer (fills LDSM latency),
// then the MMAs. One __syncwarp per chunk for cross-lane store->ldmatrix
// visibility. Buffer reuse is safe: chunk c-1's LDSM data is consumed into
// registers by its MMAs, which precede this chunk's stores in program order.
// B fragments: hi+lo fused in ONE ldmatrix.x4 (lane groups 0-15 -> Wh rows,
// 16-31 -> Wl rows), halving B LDSM instructions.
// MODE 0: in = x,            out = g_h
// MODE 1: in = g_h,          out = g_T, zero g_acc
// MODE 2: in = lrelu(acc+h)  (writes h back), out = g_T, zero g_acc
template <int IN, int MODE>
__global__ __launch_bounds__(128) void k_kan_mma(const float* __restrict__ xin, int layer) {
    constexpr int K = IN * 8;
    constexpr int NCH = IN / 4;             // 32-k chunks (4 inputs each)
    constexpr int WBYTES = K * 64;          // weight tile bytes (one of hi/lo)
    constexpr int PH_PITCH = 80;            // 64B row + 16B pad
    constexpr int PH_PLANE = 32 * PH_PITCH; // 2560B per plane
    constexpr int PH_BUF = 2 * PH_PLANE;    // hi+lo planes, one buffer = 5120B
    constexpr int PH_WARP = 2 * PH_BUF;     // double buffered = 10240B per warp
    extern __shared__ char smem[];
    const uint32_t SB = smem_u32(smem);
    const uint32_t SM_WH = 0, SM_WL = WBYTES, SM_PH = 2 * WBYTES;

    int tid = threadIdx.x;
    int w = tid >> 5, lane = tid & 31;

    // ---- stage weights (permuted 32-bit word copy) ----
    const __nv_bfloat16* Wh = (MODE == 0) ? g_W1h : (g_Wch + layer * 8192);
    const __nv_bfloat16* Wl = (MODE == 0) ? g_W1l : (g_Wcl + layer * 8192);
    const uint32_t* WhU = (const uint32_t*)Wh;
    const uint32_t* WlU = (const uint32_t*)Wl;
    uint32_t* swh = (uint32_t*)(smem + SM_WH);
    uint32_t* swl = (uint32_t*)(smem + SM_WL);
    for (int wdx = tid; wdx < K * 16; wdx += 128) {
        int kt = wdx >> 8;                  // 256 words per k16-tile
        int o = (wdx >> 3) & 31;
        int seg = wdx & 7;
        int src = (o * K + kt * 16 + seg * 2) >> 1;
        int dst = (kt * 32 + o) * 8 + seg;
        swh[dst] = WhU[src];
        swl[dst] = WlU[src];
    }
    __syncthreads();

    // ---- per-lane constant addresses ----
    int node = blockIdx.x * 128 + w * 32 + lane;
    int nodeC = node < N_NODES ? node : N_NODES - 1;
    bool nvalid = node < N_NODES;
    const uint32_t phiWarp = SB + SM_PH + w * PH_WARP;
    // A-ldmatrix row for this lane (row-group 0; group 1 at +16*80)
    int ar = (lane & 7) + (lane & 8);
    const uint32_t aOff = (uint32_t)(ar * PH_PITCH + (lane >> 4) * 16);
    // fused hi/lo B-ldmatrix per-lane base: lanes 0-15 -> Wh, 16-31 -> Wl
    const uint32_t bBase = SB + (lane < 16 ? SM_WH : SM_WL)
                         + (uint32_t)((lane & 7) * 32 + ((lane >> 3) & 1) * 16);

    // trig+pack+store for chunk c into buffer buf
    auto phi_chunk = [&](int c, int buf) {
        float4 xv4;
        if (MODE == 0) {
            xv4 = __ldg((const float4*)(xin + (size_t)nodeC * IN + c * 4));
        } else if (MODE == 1) {
            xv4 = *(const float4*)(g_h + nodeC * HID + c * 4);
        } else {
            float4* hp = (float4*)(g_h + nodeC * HID + c * 4);
            const float4* ap = (const float4*)(g_acc + nodeC * HID + c * 4);
            float4 m = *ap, h = *hp;
            xv4.x = lrelu(m.x + h.x); xv4.y = lrelu(m.y + h.y);
            xv4.z = lrelu(m.z + h.z); xv4.w = lrelu(m.w + h.w);
            if (nvalid) *hp = xv4;          // h_{l+1} writeback (exclusive lane)
        }
        uint32_t rowH = phiWarp + buf * PH_BUF + lane * PH_PITCH;
        uint32_t rowL = rowH + PH_PLANE;
#pragma unroll
        for (int u = 0; u < 4; u++) {
            float xv = (&xv4.x)[u];
            float s1, c1;
            __sincosf(xv, &s1, &c1);
            float t2 = c1 + c1;
            float c2 = fmaf(t2, c1, -1.f), s2 = t2 * s1;
            float c3 = fmaf(t2, c2, -c1),  s3 = fmaf(t2, s2, -s1);
            float c4 = fmaf(t2, c3, -c2),  s4 = fmaf(t2, s3, -s2);
            float v[8] = { c1, c2, c3, c4, s1, s2, s3, s4 };
            uint32_t hw[4], lw[4];
#pragma unroll
            for (int j = 0; j < 4; j++) {
                hw[j] = bfpack(v[2 * j], v[2 * j + 1]);
                float r0 = v[2 * j]     - __uint_as_float(hw[j] << 16);
                float r1 = v[2 * j + 1] - __uint_as_float(hw[j] & 0xFFFF0000u);
                lw[j] = bfpack(r0, r1);
            }
            asm volatile("st.shared.v4.b32 [%0], {%1,%2,%3,%4};"
                         :: "r"(rowH + u * 16), "r"(hw[0]), "r"(hw[1]), "r"(hw[2]), "r"(hw[3]) : "memory");
            asm volatile("st.shared.v4.b32 [%0], {%1,%2,%3,%4};"
                         :: "r"(rowL + u * 16), "r"(lw[0]), "r"(lw[1]), "r"(lw[2]), "r"(lw[3]) : "memory");
        }
    };

    float acc[2][4][4];
#pragma unroll
    for (int gp = 0; gp < 2; gp++)
#pragma unroll
        for (int nt = 0; nt < 4; nt++)
#pragma unroll
            for (int j = 0; j < 4; j++) acc[gp][nt][j] = 0.f;

    phi_chunk(0, 0);                        // prologue

#pragma unroll 1
    for (int c = 0; c < NCH; c++) {
        __syncwarp();                       // Phi stores -> ldmatrix visibility
        int buf = c & 1;
        uint32_t aH = phiWarp + buf * PH_BUF + aOff;
        uint32_t aL = aH + PH_PLANE;

        // A fragments for both k16 steps (volatile order: issued first)
        uint32_t ah0[2][4], ah1[2][4], al0[2][4], al1[2][4];
#pragma unroll
        for (int kk = 0; kk < 2; kk++) {
            ldmatrix_x4(ah0[kk], aH + kk * 32);
            ldmatrix_x4(ah1[kk], aH + 16 * PH_PITCH + kk * 32);
            ldmatrix_x4(al0[kk], aL + kk * 32);
            ldmatrix_x4(al1[kk], aL + 16 * PH_PITCH + kk * 32);
        }

        // overlap: next chunk's trig fills the LDSM latency
        if (c + 1 < NCH) phi_chunk(c + 1, buf ^ 1);

        // MMAs (B frags: one fused hi/lo ldmatrix.x4 per n-tile per k16)
#pragma unroll
        for (int kk = 0; kk < 2; kk++) {
            uint32_t bt = bBase + (uint32_t)((c * 2 + kk) * 1024);
#pragma unroll
            for (int nt = 0; nt < 4; nt++) {
                uint32_t bb[4];             // {bh0, bh1, bl0, bl1}
                ldmatrix_x4(bb, bt + nt * 256);
                mma16816(acc[0][nt], ah0[kk], bb[0], bb[1]);
                mma16816(acc[0][nt], ah0[kk], bb[2], bb[3]);
                mma16816(acc[0][nt], al0[kk], bb[0], bb[1]);
                mma16816(acc[1][nt], ah1[kk], bb[0], bb[1]);
                mma16816(acc[1][nt], ah1[kk], bb[2], bb[3]);
                mma16816(acc[1][nt], al1[kk], bb[0], bb[1]);
            }
        }
    }

    // ---- write D ----
    float* outbase = (MODE == 0) ? g_h : g_T;
    int gq = lane >> 2, tg = lane & 3;
#pragma unroll
    for (int gp = 0; gp < 2; gp++) {
        int row0 = blockIdx.x * 128 + w * 32 + gp * 16 + gq;
        int row1 = row0 + 8;
        if (row0 < N_NODES) {
            float* p = outbase + row0 * HID + 2 * tg;
#pragma unroll
            for (int nt = 0; nt < 4; nt++)
                *(float2*)(p + nt * 8) = make_float2(acc[gp][nt][0], acc[gp][nt][1]);
        }
        if (row1 < N_NODES) {
            float* p = outbase + row1 * HID + 2 * tg;
#pragma unroll
            for (int nt = 0; nt < 4; nt++)
                *(float2*)(p + nt * 8) = make_float2(acc[gp][nt][2], acc[gp][nt][3]);
        }
    }
    if (MODE != 0 && nvalid) {   // zero scatter buffer row (exclusive lane)
        float4 z = make_float4(0.f, 0.f, 0.f, 0.f);
        float4* az = (float4*)(g_acc + node * HID);
#pragma unroll
        for (int j = 0; j < 8; j++) az[j] = z;
    }
}

// ---------------- edge scatter: acc[dst] += T[src] --------------------------
__global__ void k_scatter(const void* __restrict__ ei, int E) {
    long long gid = (long long)blockIdx.x * blockDim.x + threadIdx.x;
    int e = (int)(gid >> 3);
    int q = (int)(gid & 7);
    if (e >= E) return;
    int is64 = g_is64;
    int src = ldidx(ei, e, is64);
    int dst = ldidx(ei, (long long)E + e, is64);
    float4 v = __ldg((const float4*)g_T + src * (HID / 4) + q);
    float* p = g_acc + dst * HID + q * 4;
    asm volatile("red.global.add.v4.f32 [%0], {%1, %2, %3, %4};"
                 :: "l"(p), "f"(v.x), "f"(v.y), "f"(v.z), "f"(v.w)
                 : "memory");
}

// ---------------- pooling (fused final leaky-relu + residual) ---------------
__global__ void k_pool(const void* __restrict__ batch) {
    int warp = (blockIdx.x * blockDim.x + threadIdx.x) >> 5;
    int lane = threadIdx.x & 31;
    if (warp >= N_NODES) return;
    int b = ldidx(batch, warp, g_is64);
    float m = g_acc[warp * HID + lane];
    float h = g_h[warp * HID + lane];
    float v = lrelu(m + h);
    atomicAdd(&g_sums[b * HID + lane], v);
    if (lane == 0) atomicAdd(&g_cnt[b], 1.f);
}

// ---------------- readout: sigmoid(KAN_linear(mean_pool)) -------------------
__global__ void k_readout(const float* __restrict__ Wout,
                          const float* __restrict__ bout,
                          float* __restrict__ out) {
    int g = threadIdx.x;
    if (g >= NG) return;
    float cnt = fmaxf(g_cnt[g], 1.f);
    float inv = 1.f / cnt;
    float acc = 0.f;
#pragma unroll
    for (int c = 0; c < HID; c++) {
        float y = g_sums[g * HID + c] * inv;
        float s, co;
        __sincosf(y, &s, &co);
        acc = fmaf(co, Wout[c], acc);
        acc = fmaf(s, Wout[HID + c], acc);
    }
    acc += bout[0];
    out[g] = 1.f / (1.f + __expf(-acc));
}

// ---------------- launch ----------------------------------------------------
extern "C" void kernel_launch(void* const* d_in, const int* in_sizes, int n_in,
                              void* d_out, int out_size) {
    const float* x      = (const float*)d_in[0];
    const void*  ei     = d_in[1];
    const void*  batch  = d_in[2];
    const float* W_in   = (const float*)d_in[3];
    const float* W_conv = (const float*)d_in[4];
    const float* W_out  = (const float*)d_in[5];
    const float* b_out  = (const float*)d_in[6];
    float* out = (float*)d_out;

    int E = in_sizes[1] / 2;

    const int SM1 = 2 * 512 * 64 + 4 * 10240;   // 65536 + 40960 = 106496
    const int SMC = 2 * 256 * 64 + 4 * 10240;   // 32768 + 40960 = 73728
    cudaFuncSetAttribute(k_kan_mma<IN_FEAT, 0>, cudaFuncAttributeMaxDynamicSharedMemorySize, SM1);
    cudaFuncSetAttribute(k_kan_mma<HID, 1>,     cudaFuncAttributeMaxDynamicSharedMemorySize, SMC);
    cudaFuncSetAttribute(k_kan_mma<HID, 2>,     cudaFuncAttributeMaxDynamicSharedMemorySize, SMC);

    k_init<<<16, 256>>>(ei);
    k_prep<<<128, 256>>>(W_in, W_conv);

    int nb = (N_NODES + 127) / 128;        // 391 tiles of 128 nodes
    long long tthreads = (long long)E * 8;
    int sb = (int)((tthreads + 255) / 256);

    k_kan_mma<IN_FEAT, 0><<<nb, 128, SM1>>>(x, 0);

    k_kan_mma<HID, 1><<<nb, 128, SMC>>>(nullptr, 0);
    k_scatter<<<sb, 256>>>(ei, E);

    k_kan_mma<HID, 2><<<nb, 128, SMC>>>(nullptr, 1);
    k_scatter<<<sb, 256>>>(ei, E);

    k_pool<<<(N_NODES + 7) / 8, 256>>>(batch);
    k_readout<<<1, 128>>>(W_out, b_out, out);
}